// round 11
// baseline (speedup 1.0000x reference)
#include <cuda_runtime.h>
#include <cuda_bf16.h>

#define NZg    192
#define PLANEg (192 * 192)
#define VOLg   (192 * 192 * 192)

#define TYB     8                    // y rows per block
#define THREADS (48 * TYB)           // 384
#define SEG     32                   // x planes per block
#define NXSEG   (192 / SEG)          // 6
#define NYT     (192 / TYB)          // 24
#define NPART   (NYT * NXSEG * 2)    // 288 block partials
#define NVOX    14155776.0           // 2 * 192^3

__device__ float        g_partials[NPART];
__device__ unsigned int g_count;     // zero at load; last block resets each launch

__device__ __forceinline__ float4 ld4(const float* __restrict__ p) {
    return *reinterpret_cast<const float4*>(p);
}

__device__ __forceinline__ float robustf(float x) {
    float ax = fabsf(x);
    return (ax <= 0.01f) ? 0.5f * x * x : 0.01f * (ax - 0.005f);
}

__device__ __forceinline__ float voxel_contrib(
    float ux, float uy, float uz,
    float vx, float vy, float vz,
    float wx, float wy, float wz)
{
    float exy = 0.5f * (uy + vx);
    float exz = 0.5f * (uz + wx);
    float eyz = 0.5f * (vz + wy);
    float tr  = ux + vy + wz;
    float rt  = robustf(tr);
    float rxx = robustf(ux), ryy = robustf(vy), rzz = robustf(wz);
    float rxy = robustf(exy), rxz = robustf(exz), ryz = robustf(eyz);
    float energy = 0.5f * rt * rt
                 + 0.5f * (rxx * rxx + ryy * ryy + rzz * rzz
                           + 2.0f * (rxy * rxy + rxz * rxz + ryz * ryz));
    // Exactly as written in the reference (NOT the textbook determinant).
    float jac = (1.0f + ux) * ((1.0f + vy) * (1.0f + wz) - vz * wy)
              - uy * (vx * (1.0f + wz) - vz * (1.0f + wx))
              + uz * (vx * wy - (1.0f + vy) * (1.0f + wx));
    return energy + 0.1f * fmaxf(-jac, 0.0f);
}

// One x-plane (4 z-voxels x 3 channels). sx is a compile-time literal at every
// call site -> FFMA-imm fast path in the interior, no boundary selects.
__device__ __forceinline__ float plane_contrib(
    const float4 a[3], const float4 c[3], const float4 n[3],
    const float4 ymv[3], const float4 ypv[3],
    const float zmv[3], const float zpv[3],
    float sx, float sy, int zq)
{
    float4 GX[3], GY[3], GZ[3];
    #pragma unroll
    for (int ch = 0; ch < 3; ++ch) {
        const float4 cc = c[ch];
        GX[ch].x = (n[ch].x - a[ch].x) * sx;
        GX[ch].y = (n[ch].y - a[ch].y) * sx;
        GX[ch].z = (n[ch].z - a[ch].z) * sx;
        GX[ch].w = (n[ch].w - a[ch].w) * sx;

        GY[ch].x = (ypv[ch].x - ymv[ch].x) * sy;
        GY[ch].y = (ypv[ch].y - ymv[ch].y) * sy;
        GY[ch].z = (ypv[ch].z - ymv[ch].z) * sy;
        GY[ch].w = (ypv[ch].w - ymv[ch].w) * sy;

        GZ[ch].x = (zq > 0)  ? (cc.y - zmv[ch]) * 0.5f : (cc.y - cc.x);
        GZ[ch].y = (cc.z - cc.x) * 0.5f;
        GZ[ch].z = (cc.w - cc.y) * 0.5f;
        GZ[ch].w = (zq < 47) ? (zpv[ch] - cc.z) * 0.5f : (cc.w - cc.z);
    }
    float s;
    s  = voxel_contrib(GX[0].x, GY[0].x, GZ[0].x,
                       GX[1].x, GY[1].x, GZ[1].x,
                       GX[2].x, GY[2].x, GZ[2].x);
    s += voxel_contrib(GX[0].y, GY[0].y, GZ[0].y,
                       GX[1].y, GY[1].y, GZ[1].y,
                       GX[2].y, GY[2].y, GZ[2].y);
    s += voxel_contrib(GX[0].z, GY[0].z, GZ[0].z,
                       GX[1].z, GY[1].z, GZ[1].z,
                       GX[2].z, GY[2].z, GZ[2].z);
    s += voxel_contrib(GX[0].w, GY[0].w, GZ[0].w,
                       GX[1].w, GY[1].w, GZ[1].w,
                       GX[2].w, GY[2].w, GZ[2].w);
    return s;
}

__global__ __launch_bounds__(THREADS, 2)
void elastic_march(const float* __restrict__ df, float* __restrict__ out)
{
    const int tid = threadIdx.x;
    const int zq  = tid % 48;                 // z float4 group, z0 = 4*zq
    const int yy  = tid / 48;                 // 0..TYB-1
    const int y   = blockIdx.x * TYB + yy;    // 0..191
    const int xs  = blockIdx.y * SEG;
    const int b   = blockIdx.z;
    const bool first = (blockIdx.y == 0);
    const bool last  = (blockIdx.y == NXSEG - 1);

    const float sy  = (y > 0 && y < 191) ? 0.5f : 1.0f;
    const int   dym = (y > 0)   ? -NZg : 0;   // per-thread constant element offsets
    const int   dyp = (y < 191) ?  NZg : 0;

    // Marching per-channel pointers at (x, y, z0); all loads are [p +/- const].
    const float* __restrict__ p0 =
        df + (size_t)b * 3 * VOLg + (size_t)xs * PLANEg + (size_t)y * NZg + 4 * zq;
    const float* pch[3] = { p0, p0 + VOLg, p0 + 2 * VOLg };

    float4 a[3], c[3];
    #pragma unroll
    for (int ch = 0; ch < 3; ++ch) {
        c[ch] = ld4(pch[ch]);
        a[ch] = first ? c[ch] : ld4(pch[ch] - PLANEg);
    }

    float acc = 0.0f;

    // ---- prologue: x = 0 (first segment only): a == c, sx = 1 ----
    if (first) {
        float4 n[3], ymv[3], ypv[3]; float zmv[3], zpv[3];
        #pragma unroll
        for (int ch = 0; ch < 3; ++ch) {
            n[ch]   = ld4(pch[ch] + PLANEg);
            ymv[ch] = ld4(pch[ch] + dym);
            ypv[ch] = ld4(pch[ch] + dyp);
            zmv[ch] = (zq > 0)  ? pch[ch][-1] : 0.0f;
            zpv[ch] = (zq < 47) ? pch[ch][4]  : 0.0f;
        }
        acc += plane_contrib(a, c, n, ymv, ypv, zmv, zpv, 1.0f, sy, zq);
        #pragma unroll
        for (int ch = 0; ch < 3; ++ch) { a[ch] = c[ch]; c[ch] = n[ch]; pch[ch] += PLANEg; }
    }

    // ---- interior: compile-time sx = 0.5, pure immediate-offset loads ----
    const int nk = SEG - (first ? 1 : 0) - (last ? 1 : 0);
    #pragma unroll 4
    for (int k = 0; k < nk; ++k) {
        float4 n[3], ymv[3], ypv[3]; float zmv[3], zpv[3];
        #pragma unroll
        for (int ch = 0; ch < 3; ++ch) {
            n[ch]   = ld4(pch[ch] + PLANEg);
            ymv[ch] = ld4(pch[ch] + dym);
            ypv[ch] = ld4(pch[ch] + dyp);
            zmv[ch] = (zq > 0)  ? pch[ch][-1] : 0.0f;
            zpv[ch] = (zq < 47) ? pch[ch][4]  : 0.0f;
        }
        acc += plane_contrib(a, c, n, ymv, ypv, zmv, zpv, 0.5f, sy, zq);
        #pragma unroll
        for (int ch = 0; ch < 3; ++ch) { a[ch] = c[ch]; c[ch] = n[ch]; pch[ch] += PLANEg; }
    }

    // ---- epilogue: x = 191 (last segment only): n == c, sx = 1 ----
    if (last) {
        float4 ymv[3], ypv[3]; float zmv[3], zpv[3];
        #pragma unroll
        for (int ch = 0; ch < 3; ++ch) {
            ymv[ch] = ld4(pch[ch] + dym);
            ypv[ch] = ld4(pch[ch] + dyp);
            zmv[ch] = (zq > 0)  ? pch[ch][-1] : 0.0f;
            zpv[ch] = (zq < 47) ? pch[ch][4]  : 0.0f;
        }
        acc += plane_contrib(a, c, c, ymv, ypv, zmv, zpv, 1.0f, sy, zq);
    }

    // ---- block reduction: warp shuffle -> shared -> warp 0 ----
    __shared__ float  swarp[32];
    __shared__ bool   s_last;
    __shared__ double sdw[32];

    const int lane = tid & 31;
    const int wid  = tid >> 5;                 // 12 warps

    #pragma unroll
    for (int o = 16; o > 0; o >>= 1)
        acc += __shfl_xor_sync(0xffffffffu, acc, o);
    if (lane == 0) swarp[wid] = acc;
    __syncthreads();

    if (tid < 32) {
        float v = (tid < THREADS / 32) ? swarp[tid] : 0.0f;
        #pragma unroll
        for (int o = 16; o > 0; o >>= 1)
            v += __shfl_xor_sync(0xffffffffu, v, o);
        if (tid == 0) {
            const int bid = blockIdx.x + NYT * (blockIdx.y + NXSEG * blockIdx.z);
            g_partials[bid] = v;
            __threadfence();
            unsigned old = atomicAdd(&g_count, 1u);
            s_last = (old == NPART - 1);
        }
    }
    __syncthreads();

    // ---- last block: deterministic final sum in double ----
    if (s_last) {
        double d = (tid < NPART) ? (double)__ldcg(&g_partials[tid]) : 0.0;
        #pragma unroll
        for (int o = 16; o > 0; o >>= 1)
            d += __shfl_xor_sync(0xffffffffu, d, o);
        if (lane == 0) sdw[wid] = d;
        __syncthreads();
        if (tid < 32) {
            double v = (tid < THREADS / 32) ? sdw[tid] : 0.0;
            #pragma unroll
            for (int o = 16; o > 0; o >>= 1)
                v += __shfl_xor_sync(0xffffffffu, v, o);
            if (tid == 0) {
                g_count = 0;                   // reset for graph replay
                out[0] = (float)(v / NVOX);
            }
        }
    }
}

extern "C" void kernel_launch(void* const* d_in, const int* in_sizes, int n_in,
                              void* d_out, int out_size) {
    const float* df = (const float*)d_in[0];
    dim3 grid(NYT, NXSEG, 2);   // 24 x 6 x 2 = 288 blocks, ~2/SM, one wave
    elastic_march<<<grid, THREADS>>>(df, (float*)d_out);
}

// round 12
// speedup vs baseline: 1.0509x; 1.0509x over previous
#include <cuda_runtime.h>
#include <cuda_bf16.h>

#define NZg    192
#define PLANEg (192 * 192)
#define VOLg   (192 * 192 * 192)

#define TYB     8                    // y rows per block
#define THREADS (48 * TYB)           // 384
#define SEG     32                   // x planes per block
#define NXSEG   (192 / SEG)          // 6
#define NYT     (192 / TYB)          // 24
#define NPART   (NYT * NXSEG * 2)    // 288 block partials
#define NVOX    14155776.0           // 2 * 192^3

__device__ float        g_partials[NPART];
__device__ unsigned int g_count;     // zero at load; last block resets each launch

__device__ __forceinline__ float4 ld4(const float* __restrict__ p) {
    return *reinterpret_cast<const float4*>(p);
}

__device__ __forceinline__ float robustf(float x) {
    float ax = fabsf(x);
    return (ax <= 0.01f) ? 0.5f * x * x : 0.01f * (ax - 0.005f);
}

__device__ __forceinline__ float voxel_contrib(
    float ux, float uy, float uz,
    float vx, float vy, float vz,
    float wx, float wy, float wz)
{
    float exy = 0.5f * (uy + vx);
    float exz = 0.5f * (uz + wx);
    float eyz = 0.5f * (vz + wy);
    float tr  = ux + vy + wz;
    float rt  = robustf(tr);
    float rxx = robustf(ux), ryy = robustf(vy), rzz = robustf(wz);
    float rxy = robustf(exy), rxz = robustf(exz), ryz = robustf(eyz);
    float energy = 0.5f * rt * rt
                 + 0.5f * (rxx * rxx + ryy * ryy + rzz * rzz
                           + 2.0f * (rxy * rxy + rxz * rxz + ryz * ryz));
    // Exactly as written in the reference (NOT the textbook determinant).
    float jac = (1.0f + ux) * ((1.0f + vy) * (1.0f + wz) - vz * wy)
              - uy * (vx * (1.0f + wz) - vz * (1.0f + wx))
              + uz * (vx * wy - (1.0f + vy) * (1.0f + wx));
    return energy + 0.1f * fmaxf(-jac, 0.0f);
}

// One x-plane (4 z-voxels x 3 channels). sx is a compile-time literal at
// every call site.
__device__ __forceinline__ float plane_contrib(
    const float4 a[3], const float4 c[3], const float4 n[3],
    const float4 ymv[3], const float4 ypv[3],
    const float zmv[3], const float zpv[3],
    float sx, float sy, int zq)
{
    float4 GX[3], GY[3], GZ[3];
    #pragma unroll
    for (int ch = 0; ch < 3; ++ch) {
        const float4 cc = c[ch];
        GX[ch].x = (n[ch].x - a[ch].x) * sx;
        GX[ch].y = (n[ch].y - a[ch].y) * sx;
        GX[ch].z = (n[ch].z - a[ch].z) * sx;
        GX[ch].w = (n[ch].w - a[ch].w) * sx;

        GY[ch].x = (ypv[ch].x - ymv[ch].x) * sy;
        GY[ch].y = (ypv[ch].y - ymv[ch].y) * sy;
        GY[ch].z = (ypv[ch].z - ymv[ch].z) * sy;
        GY[ch].w = (ypv[ch].w - ymv[ch].w) * sy;

        GZ[ch].x = (zq > 0)  ? (cc.y - zmv[ch]) * 0.5f : (cc.y - cc.x);
        GZ[ch].y = (cc.z - cc.x) * 0.5f;
        GZ[ch].z = (cc.w - cc.y) * 0.5f;
        GZ[ch].w = (zq < 47) ? (zpv[ch] - cc.z) * 0.5f : (cc.w - cc.z);
    }
    float s;
    s  = voxel_contrib(GX[0].x, GY[0].x, GZ[0].x,
                       GX[1].x, GY[1].x, GZ[1].x,
                       GX[2].x, GY[2].x, GZ[2].x);
    s += voxel_contrib(GX[0].y, GY[0].y, GZ[0].y,
                       GX[1].y, GY[1].y, GZ[1].y,
                       GX[2].y, GY[2].y, GZ[2].y);
    s += voxel_contrib(GX[0].z, GY[0].z, GZ[0].z,
                       GX[1].z, GY[1].z, GZ[1].z,
                       GX[2].z, GY[2].z, GZ[2].z);
    s += voxel_contrib(GX[0].w, GY[0].w, GZ[0].w,
                       GX[1].w, GY[1].w, GZ[1].w,
                       GX[2].w, GY[2].w, GZ[2].w);
    return s;
}

__global__ __launch_bounds__(THREADS, 2)
void elastic_march(const float* __restrict__ df, float* __restrict__ out)
{
    const int tid = threadIdx.x;
    const int zq  = tid % 48;                 // z float4 group, z0 = 4*zq
    const int yy  = tid / 48;                 // 0..TYB-1
    const int y   = blockIdx.x * TYB + yy;    // 0..191
    const int xs  = blockIdx.y * SEG;
    const int b   = blockIdx.z;
    const bool first = (blockIdx.y == 0);
    const bool last  = (blockIdx.y == NXSEG - 1);

    const float sy  = (y > 0 && y < 191) ? 0.5f : 1.0f;
    const int   dym = (y > 0)   ? -NZg : 0;   // per-thread constant offsets
    const int   dyp = (y < 191) ?  NZg : 0;

    // Marching per-channel pointers at (x, y, z0); all loads are [p +/- const].
    const float* __restrict__ p0 =
        df + (size_t)b * 3 * VOLg + (size_t)xs * PLANEg + (size_t)y * NZg + 4 * zq;
    const float* pch[3] = { p0, p0 + VOLg, p0 + 2 * VOLg };

    // Software pipeline: registers hold c = plane(x), n = plane(x+1).
    float4 c[3], n[3];
    #pragma unroll
    for (int ch = 0; ch < 3; ++ch) {
        c[ch] = ld4(pch[ch]);
        n[ch] = ld4(pch[ch] + PLANEg);
    }

    float acc = 0.0f;
    int x = xs;

    // ---- prologue: x = 0 (first segment only): a == c, sx = 1 ----
    if (first) {
        float4 pf[3], ymv[3], ypv[3]; float zmv[3], zpv[3];
        #pragma unroll
        for (int ch = 0; ch < 3; ++ch) {
            pf[ch]  = ld4(pch[ch] + 2 * PLANEg);     // prefetch plane 2
            ymv[ch] = ld4(pch[ch] + dym);
            ypv[ch] = ld4(pch[ch] + dyp);
            zmv[ch] = (zq > 0)  ? pch[ch][-1] : 0.0f;
            zpv[ch] = (zq < 47) ? pch[ch][4]  : 0.0f;
        }
        acc += plane_contrib(c, c, n, ymv, ypv, zmv, zpv, 1.0f, sy, zq);
        #pragma unroll
        for (int ch = 0; ch < 3; ++ch) { c[ch] = n[ch]; n[ch] = pf[ch]; pch[ch] += PLANEg; }
        x = 1;
    }

    // ---- interior: sx = 0.5 literal; pf(x+2) issued first (DRAM latency
    //      overlapped with this plane's compute); a(x-1) reloaded from L1 ----
    const int x_end = last ? 191 : xs + SEG;
    #pragma unroll 1
    for (; x < x_end; ++x) {
        const int off2 = (x + 2 <= 191) ? 2 * PLANEg : PLANEg;  // clamp; value unused when clamped
        float4 pf[3], a[3], ymv[3], ypv[3]; float zmv[3], zpv[3];
        #pragma unroll
        for (int ch = 0; ch < 3; ++ch)
            pf[ch]  = ld4(pch[ch] + off2);           // DRAM prefetch, issued first
        #pragma unroll
        for (int ch = 0; ch < 3; ++ch) {
            a[ch]   = ld4(pch[ch] - PLANEg);         // L1 (loaded 2 iters ago)
            ymv[ch] = ld4(pch[ch] + dym);            // L1
            ypv[ch] = ld4(pch[ch] + dyp);            // L1
            zmv[ch] = (zq > 0)  ? pch[ch][-1] : 0.0f;
            zpv[ch] = (zq < 47) ? pch[ch][4]  : 0.0f;
        }
        acc += plane_contrib(a, c, n, ymv, ypv, zmv, zpv, 0.5f, sy, zq);
        #pragma unroll
        for (int ch = 0; ch < 3; ++ch) { c[ch] = n[ch]; n[ch] = pf[ch]; pch[ch] += PLANEg; }
    }

    // ---- epilogue: x = 191 (last segment only): n == c, sx = 1 ----
    if (last) {
        float4 a[3], ymv[3], ypv[3]; float zmv[3], zpv[3];
        #pragma unroll
        for (int ch = 0; ch < 3; ++ch) {
            a[ch]   = ld4(pch[ch] - PLANEg);
            ymv[ch] = ld4(pch[ch] + dym);
            ypv[ch] = ld4(pch[ch] + dyp);
            zmv[ch] = (zq > 0)  ? pch[ch][-1] : 0.0f;
            zpv[ch] = (zq < 47) ? pch[ch][4]  : 0.0f;
        }
        acc += plane_contrib(a, c, c, ymv, ypv, zmv, zpv, 1.0f, sy, zq);
    }

    // ---- block reduction: warp shuffle -> shared -> warp 0 ----
    __shared__ float  swarp[32];
    __shared__ bool   s_last;
    __shared__ double sdw[32];

    const int lane = tid & 31;
    const int wid  = tid >> 5;                 // 12 warps

    #pragma unroll
    for (int o = 16; o > 0; o >>= 1)
        acc += __shfl_xor_sync(0xffffffffu, acc, o);
    if (lane == 0) swarp[wid] = acc;
    __syncthreads();

    if (tid < 32) {
        float v = (tid < THREADS / 32) ? swarp[tid] : 0.0f;
        #pragma unroll
        for (int o = 16; o > 0; o >>= 1)
            v += __shfl_xor_sync(0xffffffffu, v, o);
        if (tid == 0) {
            const int bid = blockIdx.x + NYT * (blockIdx.y + NXSEG * blockIdx.z);
            g_partials[bid] = v;
            __threadfence();
            unsigned old = atomicAdd(&g_count, 1u);
            s_last = (old == NPART - 1);
        }
    }
    __syncthreads();

    // ---- last block: deterministic final sum in double ----
    if (s_last) {
        double d = (tid < NPART) ? (double)__ldcg(&g_partials[tid]) : 0.0;
        #pragma unroll
        for (int o = 16; o > 0; o >>= 1)
            d += __shfl_xor_sync(0xffffffffu, d, o);
        if (lane == 0) sdw[wid] = d;
        __syncthreads();
        if (tid < 32) {
            double v = (tid < THREADS / 32) ? sdw[tid] : 0.0;
            #pragma unroll
            for (int o = 16; o > 0; o >>= 1)
                v += __shfl_xor_sync(0xffffffffu, v, o);
            if (tid == 0) {
                g_count = 0;                   // reset for graph replay
                out[0] = (float)(v / NVOX);
            }
        }
    }
}

extern "C" void kernel_launch(void* const* d_in, const int* in_sizes, int n_in,
                              void* d_out, int out_size) {
    const float* df = (const float*)d_in[0];
    dim3 grid(NYT, NXSEG, 2);   // 24 x 6 x 2 = 288 blocks, ~2/SM, one wave
    elastic_march<<<grid, THREADS>>>(df, (float*)d_out);
}